// round 9
// baseline (speedup 1.0000x reference)
#include <cuda_runtime.h>

#define LEAK 0.2f
constexpr int B_  = 2;
constexpr int C_  = 16;
constexpr int VOL = 96 * 96 * 96;
constexpr int PLN = 96 * 96;
constexpr int DVF = 48;

typedef unsigned long long pk_t;

// Scratch (device globals per harness rules).
__device__ float g_warped[(size_t)B_ * C_ * VOL];  // warped src; later fsum
__device__ float g_corr[(size_t)B_ * 27 * VOL];    // cost volume
__device__ float g_facc[(size_t)B_ * C_ * VOL];    // conv1 out (f)

__device__ __forceinline__ float lrelu(float v) { return v > 0.f ? v : LEAK * v; }

__device__ __forceinline__ pk_t pack2(float lo, float hi) {
    pk_t r; asm("mov.b64 %0, {%1,%2};" : "=l"(r) : "f"(lo), "f"(hi)); return r;
}
__device__ __forceinline__ void unpack2(pk_t p, float& lo, float& hi) {
    asm("mov.b64 {%0,%1}, %2;" : "=f"(lo), "=f"(hi) : "l"(p));
}
__device__ __forceinline__ pk_t ffma2(pk_t a, pk_t b, pk_t c) {
    pk_t d; asm("fma.rn.f32x2 %0, %1, %2, %3;" : "=l"(d) : "l"(a), "l"(b), "l"(c));
    return d;
}

// One (tap,kz) weight pair (co0,co1) applied to 4 x-pairs. A[pair*2+co].
__device__ __forceinline__ void acc8(pk_t* A, const pk_t* wt,
                                     pk_t P0, pk_t P1, pk_t P2, pk_t P3)
{
    ulonglong2 wv = *(const ulonglong2*)wt;   // 1 LDS.128 = both couts
    A[0] = ffma2(P0, wv.x, A[0]);
    A[2] = ffma2(P1, wv.x, A[2]);
    A[4] = ffma2(P2, wv.x, A[4]);
    A[6] = ffma2(P3, wv.x, A[6]);
    A[1] = ffma2(P0, wv.y, A[1]);
    A[3] = ffma2(P1, wv.y, A[3]);
    A[5] = ffma2(P2, wv.y, A[5]);
    A[7] = ffma2(P3, wv.y, A[7]);
}

// ---------------------------------------------------------------------------
// K1: trilinear upsample of dvf (48^3 -> 96^3, align_corners) + warp source
// ---------------------------------------------------------------------------
__global__ void warp_kernel(const float* __restrict__ src,
                            const float* __restrict__ dvf)
{
    int idx = blockIdx.x * blockDim.x + threadIdx.x;
    if (idx >= B_ * VOL) return;
    int b = idx / VOL;
    int r = idx - b * VOL;
    int z = r / PLN;
    int y = (r / 96) % 96;
    int x = r % 96;

    const float sc = 47.0f / 95.0f;
    float pz = z * sc, py = y * sc, px = x * sc;
    int z0 = (int)pz, y0 = (int)py, x0 = (int)px;
    int z1 = min(z0 + 1, DVF - 1), y1 = min(y0 + 1, DVF - 1), x1 = min(x0 + 1, DVF - 1);
    float wz = pz - (float)z0, wy = py - (float)y0, wx = px - (float)x0;

    const float* dv = dvf + (size_t)b * 3 * DVF * DVF * DVF;
    float flow[3];
#pragma unroll
    for (int cc = 0; cc < 3; cc++) {
        const float* p = dv + (size_t)cc * DVF * DVF * DVF;
        float v000 = __ldg(p + (z0 * 48 + y0) * 48 + x0);
        float v001 = __ldg(p + (z0 * 48 + y0) * 48 + x1);
        float v010 = __ldg(p + (z0 * 48 + y1) * 48 + x0);
        float v011 = __ldg(p + (z0 * 48 + y1) * 48 + x1);
        float v100 = __ldg(p + (z1 * 48 + y0) * 48 + x0);
        float v101 = __ldg(p + (z1 * 48 + y0) * 48 + x1);
        float v110 = __ldg(p + (z1 * 48 + y1) * 48 + x0);
        float v111 = __ldg(p + (z1 * 48 + y1) * 48 + x1);
        float v00 = v000 * (1.f - wx) + v001 * wx;
        float v01 = v010 * (1.f - wx) + v011 * wx;
        float v10 = v100 * (1.f - wx) + v101 * wx;
        float v11 = v110 * (1.f - wx) + v111 * wx;
        float v0 = v00 * (1.f - wy) + v01 * wy;
        float v1 = v10 * (1.f - wy) + v11 * wy;
        flow[cc] = v0 * (1.f - wz) + v1 * wz;
    }

    float zc = (float)z + flow[0];
    float yc = (float)y + flow[1];
    float xc = (float)x + flow[2];
    float zf = floorf(zc), yf = floorf(yc), xf = floorf(xc);
    float fz = zc - zf, fy = yc - yf, fx = xc - xf;
    int iz0 = (int)zf, iy0 = (int)yf, ix0 = (int)xf;

    int   zi[2] = { iz0, iz0 + 1 };
    int   yi[2] = { iy0, iy0 + 1 };
    int   xi[2] = { ix0, ix0 + 1 };
    float wzv[2] = { 1.f - fz, fz };
    float wyv[2] = { 1.f - fy, fy };
    float wxv[2] = { 1.f - fx, fx };

    int   idx8[8];
    float w8[8];
    int j = 0;
#pragma unroll
    for (int a = 0; a < 2; a++)
#pragma unroll
        for (int bb = 0; bb < 2; bb++)
#pragma unroll
            for (int c2 = 0; c2 < 2; c2++) {
                int zz = zi[a], yy = yi[bb], xx = xi[c2];
                bool valid = (zz >= 0 && zz < 96 && yy >= 0 && yy < 96 &&
                              xx >= 0 && xx < 96);
                int zcl = min(max(zz, 0), 95);
                int ycl = min(max(yy, 0), 95);
                int xcl = min(max(xx, 0), 95);
                idx8[j] = (zcl * 96 + ycl) * 96 + xcl;
                w8[j] = valid ? (wzv[a] * wyv[bb] * wxv[c2]) : 0.f;
                j++;
            }

    const float* sb = src + (size_t)b * C_ * VOL;
    float* ob = g_warped + (size_t)b * C_ * VOL + r;
#pragma unroll
    for (int c = 0; c < C_; c++) {
        const float* sp = sb + (size_t)c * VOL;
        float v = 0.f;
#pragma unroll
        for (int k = 0; k < 8; k++) v = fmaf(w8[k], __ldg(sp + idx8[k]), v);
        ob[(size_t)c * VOL] = v;
    }
}

// ---------------------------------------------------------------------------
// K2: 27-shift cost volume, f32x2 packed, 2 x per thread
// ---------------------------------------------------------------------------
__global__ void __launch_bounds__(256, 2) corrp_kernel(const float* __restrict__ tgt)
{
    constexpr int ZCC = 12, NZCC = 96 / ZCC;
    int bz = blockIdx.z;
    int zc = bz % NZCC; bz /= NZCC;
    int b = bz;
    int tx = threadIdx.x, ty = threadIdx.y;
    int gx = blockIdx.x * 32 + tx * 2;
    int y  = blockIdx.y * 16 + ty;
    int zs = zc * ZCC;

    const float* wb = g_warped + (size_t)b * C_ * VOL;
    const float* tb = tgt + (size_t)b * C_ * VOL;

    for (int z = zs; z < zs + ZCC; z++) {
        pk_t acc[27];
#pragma unroll
        for (int s = 0; s < 27; s++) acc[s] = 0ull;

#pragma unroll 1
        for (int ch = 0; ch < C_; ch++) {
            pk_t t2 = *(const pk_t*)(tb + (size_t)ch * VOL + (size_t)z * PLN + y * 96 + gx);
#pragma unroll
            for (int dz = 0; dz < 3; dz++) {
                int zz = z + dz - 1;
                bool vz = (zz >= 0 && zz <= 95);
#pragma unroll
                for (int dy = 0; dy < 3; dy++) {
                    int yy = y + dy - 1;
                    bool vr = vz && (yy >= 0 && yy <= 95);
                    const float* pr = wb + (size_t)ch * VOL + (size_t)zz * PLN + yy * 96 + gx;
                    float m0 = 0.f, m1 = 0.f, vl = 0.f, vrv = 0.f;
                    if (vr) {
                        float2 m = __ldg((const float2*)pr);
                        m0 = m.x; m1 = m.y;
                        if (gx > 0)  vl  = __ldg(pr - 1);
                        if (gx < 94) vrv = __ldg(pr + 2);
                    }
                    pk_t pL = pack2(vl, m0);
                    pk_t pC = pack2(m0, m1);
                    pk_t pR = pack2(m1, vrv);
                    int s = dz * 9 + dy * 3;
                    acc[s]     = ffma2(t2, pL, acc[s]);
                    acc[s + 1] = ffma2(t2, pC, acc[s + 1]);
                    acc[s + 2] = ffma2(t2, pR, acc[s + 2]);
                }
            }
        }

        float* op = g_corr + (size_t)b * 27 * VOL + (size_t)z * PLN + y * 96 + gx;
#pragma unroll
        for (int s = 0; s < 27; s++) {
            float lo, hi;
            unpack2(acc[s], lo, hi);
            lo = lrelu(lo * 0.0625f);
            hi = lrelu(hi * 0.0625f);
            *(float2*)(op + (size_t)s * VOL) = make_float2(lo, hi);
        }
    }
}

// ---------------------------------------------------------------------------
// Packed 3x3x3 conv: z-ring, XPT=8 (4 f32x2 pairs), COG=2 couts.
// Per (ci,tap,kz): ONE LDS.128 (both couts, duplicated) feeds 8 FFMA2.
// Block (4,32) -> 32x32 xy tile. Up to 3 fused CIN segments.
// COUT_TOT: number of cout groups * 2 (grid decomposition);
// COUT_STORE: real channel count used for output addressing & guarding.
// ---------------------------------------------------------------------------
template<int CIN0, int CIN1, int CIN2, int COUT_TOT, int COUT_STORE, int ZCc, bool RES>
__global__ void __launch_bounds__(128, 5) convp8_kernel(
    const float* __restrict__ in0, const float* __restrict__ in1,
    const float* __restrict__ in2,
    const float* __restrict__ w, const float* __restrict__ bias,
    float* __restrict__ out, const float* __restrict__ res)
{
    constexpr int CTOT = CIN0 + CIN1 + CIN2;
    constexpr int NCG  = COUT_TOT / 2;
    constexpr int NZCc = 96 / ZCc;
    extern __shared__ char smraw[];
    pk_t* swgt = (pk_t*)smraw;   // [ci][tap9][kz3][co2] duplicated (w,w)

    int bz = blockIdx.z;
    int zc = bz % NZCc; bz /= NZCc;
    int cg = bz % NCG;  bz /= NCG;
    int b  = bz;
    int co0 = cg * 2;

    int tid = threadIdx.y * 4 + threadIdx.x;
    for (int i = tid; i < CTOT * 27 * 2; i += 128) {
        int co = i % 2;
        int r  = i / 2;
        int kz = r % 3;
        int t  = (r / 3) % 9;
        int ci = r / 27;
        float wv = (co0 + co < COUT_STORE)
            ? __ldg(w + ((size_t)(co0 + co) * CTOT + ci) * 27 + kz * 9 + t) : 0.f;
        swgt[i] = pack2(wv, wv);
    }
    __syncthreads();

    int gx = blockIdx.x * 32 + threadIdx.x * 8;
    int y  = blockIdx.y * 32 + threadIdx.y;
    int zs = zc * ZCc;

    const float* base0 = in0 + (size_t)b * CIN0 * VOL;
    const float* base1 = (CIN1 > 0) ? in1 + (size_t)b * CIN1 * VOL : nullptr;
    const float* base2 = (CIN2 > 0) ? in2 + (size_t)b * CIN2 * VOL : nullptr;

    // acc slot = 8 pk_t: [pair0co0, pair0co1, pair1co0, ... pair3co1]
    pk_t a0[8], a1[8], a2[8];
#pragma unroll
    for (int i = 0; i < 8; i++) { a0[i] = 0ull; a1[i] = 0ull; a2[i] = 0ull; }

#define SEG_LOOP(BASE, CINSEG, CIOFF, AP, AC, AN)                              \
    _Pragma("unroll 1")                                                        \
    for (int ci = 0; ci < (CINSEG); ci++) {                                    \
        const float* p = (BASE) + ((size_t)ci) * VOL + (size_t)z * PLN +       \
                         y * 96 + gx;                                          \
        const pk_t* wci = swgt + (size_t)((CIOFF) + ci) * 54;                  \
        _Pragma("unroll")                                                      \
        for (int dy = 0; dy < 3; dy++) {                                       \
            int yy = y + dy - 1;                                               \
            bool vy = (yy >= 0 && yy <= 95);                                   \
            const float* pr = p + (dy - 1) * 96;                               \
            float4 A = make_float4(0.f, 0.f, 0.f, 0.f);                        \
            float4 Bq = make_float4(0.f, 0.f, 0.f, 0.f);                       \
            float vl = 0.f, vr = 0.f;                                          \
            if (vy) {                                                          \
                A  = __ldg((const float4*)pr);                                 \
                Bq = __ldg((const float4*)(pr + 4));                           \
                if (gx > 0)  vl = __ldg(pr - 1);                               \
                if (gx < 88) vr = __ldg(pr + 8);                               \
            }                                                                  \
            pk_t e0 = pack2(A.x, A.y),   e1 = pack2(A.z, A.w);                 \
            pk_t e2 = pack2(Bq.x, Bq.y), e3 = pack2(Bq.z, Bq.w);               \
            pk_t s0 = pack2(vl, A.x),    s1 = pack2(A.y, A.z);                 \
            pk_t s2 = pack2(A.w, Bq.x),  s3 = pack2(Bq.y, Bq.z);               \
            pk_t s4 = pack2(Bq.w, vr);                                         \
            _Pragma("unroll")                                                  \
            for (int kx = 0; kx < 3; kx++) {                                   \
                pk_t P0 = (kx == 0) ? s0 : (kx == 1) ? e0 : s1;                \
                pk_t P1 = (kx == 0) ? s1 : (kx == 1) ? e1 : s2;                \
                pk_t P2 = (kx == 0) ? s2 : (kx == 1) ? e2 : s3;                \
                pk_t P3 = (kx == 0) ? s3 : (kx == 1) ? e3 : s4;                \
                const pk_t* wt = wci + (size_t)(dy * 3 + kx) * 6;              \
                acc8(AN, wt,     P0, P1, P2, P3);                              \
                acc8(AC, wt + 2, P0, P1, P2, P3);                              \
                acc8(AP, wt + 4, P0, P1, P2, P3);                              \
            }                                                                  \
        }                                                                      \
    }

#define CONV_STEP(ZP, AP, AC, AN)                                              \
    {                                                                          \
        int z = (ZP);                                                          \
        if (z >= 0 && z <= 95 && z <= zs + ZCc) {                              \
            SEG_LOOP(base0, CIN0, 0, AP, AC, AN);                              \
            if (CIN1 > 0) { SEG_LOOP(base1, CIN1, CIN0, AP, AC, AN); }         \
            if (CIN2 > 0) { SEG_LOOP(base2, CIN2, CIN0 + CIN1, AP, AC, AN); }  \
        }                                                                      \
        int zo = z - 1;                                                        \
        if (zo >= zs && zo < zs + ZCc) {                                       \
            _Pragma("unroll")                                                  \
            for (int co = 0; co < 2; co++) {                                   \
                if (co0 + co < COUT_STORE) {                                   \
                    size_t off = ((size_t)(b * COUT_STORE + co0 + co)) * VOL + \
                                 (size_t)zo * PLN + y * 96 + gx;               \
                    float bv = __ldg(bias + co0 + co);                         \
                    float o[8];                                                \
                    unpack2(AP[co],     o[0], o[1]);                           \
                    unpack2(AP[2 + co], o[2], o[3]);                           \
                    unpack2(AP[4 + co], o[4], o[5]);                           \
                    unpack2(AP[6 + co], o[6], o[7]);                           \
                    _Pragma("unroll")                                          \
                    for (int q = 0; q < 8; q++) o[q] = lrelu(o[q] + bv);       \
                    if (RES) {                                                 \
                        float4 r0 = __ldg((const float4*)(res + off));         \
                        float4 r1 = __ldg((const float4*)(res + off + 4));     \
                        o[0] += r0.x; o[1] += r0.y; o[2] += r0.z; o[3] += r0.w;\
                        o[4] += r1.x; o[5] += r1.y; o[6] += r1.z; o[7] += r1.w;\
                    }                                                          \
                    *(float4*)(out + off)     = make_float4(o[0], o[1], o[2], o[3]); \
                    *(float4*)(out + off + 4) = make_float4(o[4], o[5], o[6], o[7]); \
                }                                                              \
            }                                                                  \
        }                                                                      \
        _Pragma("unroll")                                                      \
        for (int i = 0; i < 8; i++) AP[i] = 0ull;                              \
    }

    for (int zb = zs - 1; zb <= zs + ZCc; zb += 3) {
        CONV_STEP(zb,     a0, a1, a2);
        CONV_STEP(zb + 1, a1, a2, a0);
        CONV_STEP(zb + 2, a2, a0, a1);
    }
#undef CONV_STEP
#undef SEG_LOOP
}

// ---------------------------------------------------------------------------
extern "C" void kernel_launch(void* const* d_in, const int* in_sizes, int n_in,
                              void* d_out, int out_size)
{
    const float* src = (const float*)d_in[0];
    const float* tgt = (const float*)d_in[1];
    const float* dvf = (const float*)d_in[2];
    const float* w1  = (const float*)d_in[3];
    const float* b1  = (const float*)d_in[4];
    const float* w2  = (const float*)d_in[5];
    const float* b2  = (const float*)d_in[6];
    const float* w3  = (const float*)d_in[7];
    const float* b3  = (const float*)d_in[8];
    float* out = (float*)d_out;

    float* warped = nullptr;
    float* corr   = nullptr;
    float* facc   = nullptr;
    cudaGetSymbolAddress((void**)&warped, g_warped);
    cudaGetSymbolAddress((void**)&corr, g_corr);
    cudaGetSymbolAddress((void**)&facc, g_facc);

    const int sm1 = 59 * 27 * 2 * (int)sizeof(pk_t);   // 25488
    const int sm2 = 16 * 27 * 2 * (int)sizeof(pk_t);   //  6912

    cudaFuncSetAttribute((const void*)&convp8_kernel<16, 27, 16, 16, 16, 16, false>,
                         cudaFuncAttributeMaxDynamicSharedMemorySize, sm1);
    cudaFuncSetAttribute((const void*)&convp8_kernel<16, 0, 0, 16, 16, 16, true>,
                         cudaFuncAttributeMaxDynamicSharedMemorySize, sm2);
    cudaFuncSetAttribute((const void*)&convp8_kernel<16, 0, 0, 4, 3, 8, false>,
                         cudaFuncAttributeMaxDynamicSharedMemorySize, sm2);

    int nvox = B_ * VOL;
    warp_kernel<<<(nvox + 255) / 256, 256>>>(src, dvf);

    dim3 cblk(16, 16);
    dim3 cgrd(3, 6, 8 * B_);
    corrp_kernel<<<cgrd, cblk>>>(tgt);

    dim3 blk(4, 32);
    dim3 g1(3, 3, 6 * 8 * B_);     // ZC=16 (NZC=6), NCG=8 -> 864 blocks
    dim3 g3(3, 3, 12 * 2 * B_);    // ZC=8 (NZC=12), NCG=2 -> 432 blocks

    // conv1 fused over its 3 input segments (src, corr, tgt): 59ch -> 16ch, lrelu
    convp8_kernel<16, 27, 16, 16, 16, 16, false>
        <<<g1, blk, sm1>>>(src, corr, tgt, w1, b1, facc, nullptr);
    // conv2 + residual: fsum = f + lrelu(conv(f))
    convp8_kernel<16, 0, 0, 16, 16, 16, true>
        <<<g1, blk, sm2>>>(facc, nullptr, nullptr, w2, b2, warped, facc);
    // conv3: 16 -> 3 (grid uses COUT_TOT=4 groups; stores guarded to 3 real channels)
    convp8_kernel<16, 0, 0, 4, 3, 8, false>
        <<<g3, blk, sm2>>>(warped, nullptr, nullptr, w3, b3, out, nullptr);
}

// round 10
// speedup vs baseline: 1.5848x; 1.5848x over previous
#include <cuda_runtime.h>

#define LEAK 0.2f
constexpr int B_  = 2;
constexpr int C_  = 16;
constexpr int VOL = 96 * 96 * 96;
constexpr int PLN = 96 * 96;
constexpr int DVF = 48;

typedef unsigned long long pk_t;

// Scratch (device globals per harness rules).
__device__ float g_warped[(size_t)B_ * C_ * VOL];  // warped src; later fsum
__device__ float g_corr[(size_t)B_ * 27 * VOL];    // cost volume
__device__ float g_facc[(size_t)B_ * C_ * VOL];    // conv1 out (f)

__device__ __forceinline__ float lrelu(float v) { return v > 0.f ? v : LEAK * v; }

__device__ __forceinline__ pk_t pack2(float lo, float hi) {
    pk_t r; asm("mov.b64 %0, {%1,%2};" : "=l"(r) : "f"(lo), "f"(hi)); return r;
}
__device__ __forceinline__ void unpack2(pk_t p, float& lo, float& hi) {
    asm("mov.b64 {%0,%1}, %2;" : "=f"(lo), "=f"(hi) : "l"(p));
}
__device__ __forceinline__ pk_t ffma2(pk_t a, pk_t b, pk_t c) {
    pk_t d; asm("fma.rn.f32x2 %0, %1, %2, %3;" : "=l"(d) : "l"(a), "l"(b), "l"(c));
    return d;
}

// ---------------------------------------------------------------------------
// K1: trilinear upsample of dvf (48^3 -> 96^3, align_corners) + warp source
// ---------------------------------------------------------------------------
__global__ void warp_kernel(const float* __restrict__ src,
                            const float* __restrict__ dvf)
{
    int idx = blockIdx.x * blockDim.x + threadIdx.x;
    if (idx >= B_ * VOL) return;
    int b = idx / VOL;
    int r = idx - b * VOL;
    int z = r / PLN;
    int y = (r / 96) % 96;
    int x = r % 96;

    const float sc = 47.0f / 95.0f;
    float pz = z * sc, py = y * sc, px = x * sc;
    int z0 = (int)pz, y0 = (int)py, x0 = (int)px;
    int z1 = min(z0 + 1, DVF - 1), y1 = min(y0 + 1, DVF - 1), x1 = min(x0 + 1, DVF - 1);
    float wz = pz - (float)z0, wy = py - (float)y0, wx = px - (float)x0;

    const float* dv = dvf + (size_t)b * 3 * DVF * DVF * DVF;
    float flow[3];
#pragma unroll
    for (int cc = 0; cc < 3; cc++) {
        const float* p = dv + (size_t)cc * DVF * DVF * DVF;
        float v000 = __ldg(p + (z0 * 48 + y0) * 48 + x0);
        float v001 = __ldg(p + (z0 * 48 + y0) * 48 + x1);
        float v010 = __ldg(p + (z0 * 48 + y1) * 48 + x0);
        float v011 = __ldg(p + (z0 * 48 + y1) * 48 + x1);
        float v100 = __ldg(p + (z1 * 48 + y0) * 48 + x0);
        float v101 = __ldg(p + (z1 * 48 + y0) * 48 + x1);
        float v110 = __ldg(p + (z1 * 48 + y1) * 48 + x0);
        float v111 = __ldg(p + (z1 * 48 + y1) * 48 + x1);
        float v00 = v000 * (1.f - wx) + v001 * wx;
        float v01 = v010 * (1.f - wx) + v011 * wx;
        float v10 = v100 * (1.f - wx) + v101 * wx;
        float v11 = v110 * (1.f - wx) + v111 * wx;
        float v0 = v00 * (1.f - wy) + v01 * wy;
        float v1 = v10 * (1.f - wy) + v11 * wy;
        flow[cc] = v0 * (1.f - wz) + v1 * wz;
    }

    float zc = (float)z + flow[0];
    float yc = (float)y + flow[1];
    float xc = (float)x + flow[2];
    float zf = floorf(zc), yf = floorf(yc), xf = floorf(xc);
    float fz = zc - zf, fy = yc - yf, fx = xc - xf;
    int iz0 = (int)zf, iy0 = (int)yf, ix0 = (int)xf;

    int   zi[2] = { iz0, iz0 + 1 };
    int   yi[2] = { iy0, iy0 + 1 };
    int   xi[2] = { ix0, ix0 + 1 };
    float wzv[2] = { 1.f - fz, fz };
    float wyv[2] = { 1.f - fy, fy };
    float wxv[2] = { 1.f - fx, fx };

    int   idx8[8];
    float w8[8];
    int j = 0;
#pragma unroll
    for (int a = 0; a < 2; a++)
#pragma unroll
        for (int bb = 0; bb < 2; bb++)
#pragma unroll
            for (int c2 = 0; c2 < 2; c2++) {
                int zz = zi[a], yy = yi[bb], xx = xi[c2];
                bool valid = (zz >= 0 && zz < 96 && yy >= 0 && yy < 96 &&
                              xx >= 0 && xx < 96);
                int zcl = min(max(zz, 0), 95);
                int ycl = min(max(yy, 0), 95);
                int xcl = min(max(xx, 0), 95);
                idx8[j] = (zcl * 96 + ycl) * 96 + xcl;
                w8[j] = valid ? (wzv[a] * wyv[bb] * wxv[c2]) : 0.f;
                j++;
            }

    const float* sb = src + (size_t)b * C_ * VOL;
    float* ob = g_warped + (size_t)b * C_ * VOL + r;
#pragma unroll
    for (int c = 0; c < C_; c++) {
        const float* sp = sb + (size_t)c * VOL;
        float v = 0.f;
#pragma unroll
        for (int k = 0; k < 8; k++) v = fmaf(w8[k], __ldg(sp + idx8[k]), v);
        ob[(size_t)c * VOL] = v;
    }
}

// ---------------------------------------------------------------------------
// K2: 27-shift cost volume, f32x2 packed, 2 x per thread
// ---------------------------------------------------------------------------
__global__ void __launch_bounds__(256, 2) corrp_kernel(const float* __restrict__ tgt)
{
    constexpr int ZCC = 12, NZCC = 96 / ZCC;
    int bz = blockIdx.z;
    int zc = bz % NZCC; bz /= NZCC;
    int b = bz;
    int tx = threadIdx.x, ty = threadIdx.y;
    int gx = blockIdx.x * 32 + tx * 2;
    int y  = blockIdx.y * 16 + ty;
    int zs = zc * ZCC;

    const float* wb = g_warped + (size_t)b * C_ * VOL;
    const float* tb = tgt + (size_t)b * C_ * VOL;

    for (int z = zs; z < zs + ZCC; z++) {
        pk_t acc[27];
#pragma unroll
        for (int s = 0; s < 27; s++) acc[s] = 0ull;

#pragma unroll 1
        for (int ch = 0; ch < C_; ch++) {
            pk_t t2 = *(const pk_t*)(tb + (size_t)ch * VOL + (size_t)z * PLN + y * 96 + gx);
#pragma unroll
            for (int dz = 0; dz < 3; dz++) {
                int zz = z + dz - 1;
                bool vz = (zz >= 0 && zz <= 95);
#pragma unroll
                for (int dy = 0; dy < 3; dy++) {
                    int yy = y + dy - 1;
                    bool vr = vz && (yy >= 0 && yy <= 95);
                    const float* pr = wb + (size_t)ch * VOL + (size_t)zz * PLN + yy * 96 + gx;
                    float m0 = 0.f, m1 = 0.f, vl = 0.f, vrv = 0.f;
                    if (vr) {
                        float2 m = __ldg((const float2*)pr);
                        m0 = m.x; m1 = m.y;
                        if (gx > 0)  vl  = __ldg(pr - 1);
                        if (gx < 94) vrv = __ldg(pr + 2);
                    }
                    pk_t pL = pack2(vl, m0);
                    pk_t pC = pack2(m0, m1);
                    pk_t pR = pack2(m1, vrv);
                    int s = dz * 9 + dy * 3;
                    acc[s]     = ffma2(t2, pL, acc[s]);
                    acc[s + 1] = ffma2(t2, pC, acc[s + 1]);
                    acc[s + 2] = ffma2(t2, pR, acc[s + 2]);
                }
            }
        }

        float* op = g_corr + (size_t)b * 27 * VOL + (size_t)z * PLN + y * 96 + gx;
#pragma unroll
        for (int s = 0; s < 27; s++) {
            float lo, hi;
            unpack2(acc[s], lo, hi);
            lo = lrelu(lo * 0.0625f);
            hi = lrelu(hi * 0.0625f);
            *(float2*)(op + (size_t)s * VOL) = make_float2(lo, hi);
        }
    }
}

// ---------------------------------------------------------------------------
// Batch-packed 3x3x3 conv: f32x2 lanes = (batch0, batch1). No shifted pairs.
// COG=4 couts, 2 x-outputs per thread, z-ring. Block (16,8) -> 32x8 xy tile.
// Weights in smem: [ci][tap9][kz3][co4] duplicated (w,w), LDS.128 per 2 co.
// ---------------------------------------------------------------------------
template<int CIN0, int CIN1, int CIN2, int NCG, int COUT_STORE, int ZCc, bool RES>
__global__ void __launch_bounds__(128, 5) convb_kernel(
    const float* __restrict__ in0, const float* __restrict__ in1,
    const float* __restrict__ in2,
    const float* __restrict__ w, const float* __restrict__ bias,
    float* __restrict__ out, const float* __restrict__ res)
{
    constexpr int CTOT = CIN0 + CIN1 + CIN2;
    constexpr int NZCc = 96 / ZCc;
    extern __shared__ char smraw[];
    pk_t* swgt = (pk_t*)smraw;   // [ci][tap9][kz3][co4] duplicated

    int bz = blockIdx.z;
    int zc = bz % NZCc;
    int cg = bz / NZCc;
    int co0 = cg * 4;

    int tid = threadIdx.y * 16 + threadIdx.x;
    for (int i = tid; i < CTOT * 108; i += 128) {
        int co = i & 3;
        int kz = (i >> 2) % 3;
        int t  = (i / 12) % 9;
        int ci = i / 108;
        float wv = (co0 + co < COUT_STORE)
            ? __ldg(w + ((size_t)(co0 + co) * CTOT + ci) * 27 + kz * 9 + t) : 0.f;
        swgt[i] = pack2(wv, wv);
    }
    __syncthreads();

    int x = blockIdx.x * 32 + threadIdx.x * 2;   // this thread: outputs x, x+1
    int y = blockIdx.y * 8 + threadIdx.y;
    int zs = zc * ZCc;

    bool vxm = (x >= 1), vxp = (x <= 93);

    const float* base0 = in0;
    const float* base1 = in1;
    const float* base2 = in2;

    // acc layout: [xp*4 + co], lanes = (b0, b1)
    pk_t a0[8], a1[8], a2[8];
#pragma unroll
    for (int i = 0; i < 8; i++) { a0[i] = 0ull; a1[i] = 0ull; a2[i] = 0ull; }

    // kz0 -> AN (out z+1), kz1 -> AC (out z), kz2 -> AP (out z-1)
#define TAPFMA(S, WK, Pa, Pb)                                                  \
    {                                                                          \
        ulonglong2 wa = *(const ulonglong2*)(WK);                              \
        ulonglong2 wb = *(const ulonglong2*)((WK) + 2);                        \
        S[0] = ffma2(Pa, wa.x, S[0]);  S[4] = ffma2(Pb, wa.x, S[4]);           \
        S[1] = ffma2(Pa, wa.y, S[1]);  S[5] = ffma2(Pb, wa.y, S[5]);           \
        S[2] = ffma2(Pa, wb.x, S[2]);  S[6] = ffma2(Pb, wb.x, S[6]);           \
        S[3] = ffma2(Pa, wb.y, S[3]);  S[7] = ffma2(Pb, wb.y, S[7]);           \
    }

#define SEG_LOOP(BASE, CINSEG, CIOFF, AP, AC, AN)                              \
    _Pragma("unroll 1")                                                        \
    for (int ci = 0; ci < (CINSEG); ci++) {                                    \
        const float* q0 = (BASE) + (size_t)ci * VOL + (size_t)z * PLN +        \
                          y * 96 + x;                                          \
        const float* q1 = q0 + (size_t)(CINSEG) * VOL;                         \
        const pk_t* wci = swgt + (size_t)((CIOFF) + ci) * 108;                 \
        _Pragma("unroll")                                                      \
        for (int dy = 0; dy < 3; dy++) {                                       \
            int yy = y + dy - 1;                                               \
            bool vy = (yy >= 0 && yy <= 95);                                   \
            const float* r0 = q0 + (dy - 1) * 96;                              \
            const float* r1 = q1 + (dy - 1) * 96;                              \
            float u00 = (vy && vxm) ? __ldg(r0 - 1) : 0.f;                     \
            float u01 = vy          ? __ldg(r0)     : 0.f;                     \
            float u02 = vy          ? __ldg(r0 + 1) : 0.f;                     \
            float u03 = (vy && vxp) ? __ldg(r0 + 2) : 0.f;                     \
            float u10 = (vy && vxm) ? __ldg(r1 - 1) : 0.f;                     \
            float u11 = vy          ? __ldg(r1)     : 0.f;                     \
            float u12 = vy          ? __ldg(r1 + 1) : 0.f;                     \
            float u13 = (vy && vxp) ? __ldg(r1 + 2) : 0.f;                     \
            pk_t P0 = pack2(u00, u10);                                         \
            pk_t P1 = pack2(u01, u11);                                         \
            pk_t P2 = pack2(u02, u12);                                         \
            pk_t P3 = pack2(u03, u13);                                         \
            const pk_t* wrow = wci + dy * 36;                                  \
            _Pragma("unroll")                                                  \
            for (int kx = 0; kx < 3; kx++) {                                   \
                pk_t Pa = (kx == 0) ? P0 : (kx == 1) ? P1 : P2;                \
                pk_t Pb = (kx == 0) ? P1 : (kx == 1) ? P2 : P3;                \
                const pk_t* wk = wrow + kx * 12;                               \
                TAPFMA(AN, wk,     Pa, Pb);                                    \
                TAPFMA(AC, wk + 4, Pa, Pb);                                    \
                TAPFMA(AP, wk + 8, Pa, Pb);                                    \
            }                                                                  \
        }                                                                      \
    }

#define CONV_STEP(ZP, AP, AC, AN)                                              \
    {                                                                          \
        int z = (ZP);                                                          \
        if (z >= 0 && z <= 95 && z <= zs + ZCc) {                              \
            SEG_LOOP(base0, CIN0, 0, AP, AC, AN);                              \
            if (CIN1 > 0) { SEG_LOOP(base1, CIN1, CIN0, AP, AC, AN); }         \
            if (CIN2 > 0) { SEG_LOOP(base2, CIN2, CIN0 + CIN1, AP, AC, AN); }  \
        }                                                                      \
        int zo = z - 1;                                                        \
        if (zo >= zs && zo < zs + ZCc) {                                       \
            _Pragma("unroll")                                                  \
            for (int co = 0; co < 4; co++) {                                   \
                if (co0 + co < COUT_STORE) {                                   \
                    size_t off = (size_t)(co0 + co) * VOL +                    \
                                 (size_t)zo * PLN + y * 96 + x;                \
                    size_t bstr = (size_t)COUT_STORE * VOL;                    \
                    float bv = __ldg(bias + co0 + co);                         \
                    float p0b0, p0b1, p1b0, p1b1;                              \
                    unpack2(AP[co],     p0b0, p0b1);                           \
                    unpack2(AP[4 + co], p1b0, p1b1);                           \
                    p0b0 = lrelu(p0b0 + bv); p0b1 = lrelu(p0b1 + bv);          \
                    p1b0 = lrelu(p1b0 + bv); p1b1 = lrelu(p1b1 + bv);          \
                    if (RES) {                                                 \
                        float2 r0v = __ldg((const float2*)(res + off));        \
                        float2 r1v = __ldg((const float2*)(res + off + bstr)); \
                        p0b0 += r0v.x; p1b0 += r0v.y;                          \
                        p0b1 += r1v.x; p1b1 += r1v.y;                          \
                    }                                                          \
                    *(float2*)(out + off)        = make_float2(p0b0, p1b0);    \
                    *(float2*)(out + off + bstr) = make_float2(p0b1, p1b1);    \
                }                                                              \
            }                                                                  \
        }                                                                      \
        _Pragma("unroll")                                                      \
        for (int i = 0; i < 8; i++) AP[i] = 0ull;                              \
    }

    for (int zb = zs - 1; zb <= zs + ZCc; zb += 3) {
        CONV_STEP(zb,     a0, a1, a2);
        CONV_STEP(zb + 1, a1, a2, a0);
        CONV_STEP(zb + 2, a2, a0, a1);
    }
#undef CONV_STEP
#undef SEG_LOOP
#undef TAPFMA
}

// ---------------------------------------------------------------------------
extern "C" void kernel_launch(void* const* d_in, const int* in_sizes, int n_in,
                              void* d_out, int out_size)
{
    const float* src = (const float*)d_in[0];
    const float* tgt = (const float*)d_in[1];
    const float* dvf = (const float*)d_in[2];
    const float* w1  = (const float*)d_in[3];
    const float* b1  = (const float*)d_in[4];
    const float* w2  = (const float*)d_in[5];
    const float* b2  = (const float*)d_in[6];
    const float* w3  = (const float*)d_in[7];
    const float* b3  = (const float*)d_in[8];
    float* out = (float*)d_out;

    float* warped = nullptr;
    float* corr   = nullptr;
    float* facc   = nullptr;
    cudaGetSymbolAddress((void**)&warped, g_warped);
    cudaGetSymbolAddress((void**)&corr, g_corr);
    cudaGetSymbolAddress((void**)&facc, g_facc);

    const int sm1 = 59 * 108 * (int)sizeof(pk_t);   // 50976
    const int sm2 = 16 * 108 * (int)sizeof(pk_t);   // 13824

    cudaFuncSetAttribute((const void*)&convb_kernel<16, 27, 16, 4, 16, 12, false>,
                         cudaFuncAttributeMaxDynamicSharedMemorySize, sm1);
    cudaFuncSetAttribute((const void*)&convb_kernel<16, 0, 0, 4, 16, 12, true>,
                         cudaFuncAttributeMaxDynamicSharedMemorySize, sm2);
    cudaFuncSetAttribute((const void*)&convb_kernel<16, 0, 0, 1, 3, 6, false>,
                         cudaFuncAttributeMaxDynamicSharedMemorySize, sm2);

    int nvox = B_ * VOL;
    warp_kernel<<<(nvox + 255) / 256, 256>>>(src, dvf);

    dim3 cblk(16, 16);
    dim3 cgrd(3, 6, 8 * B_);
    corrp_kernel<<<cgrd, cblk>>>(tgt);

    dim3 blk(16, 8);
    dim3 g1(3, 12, 8 * 4);    // ZC=12 (NZC=8) x NCG=4 -> 1152 blocks
    dim3 g3(3, 12, 16 * 1);   // ZC=6 (NZC=16) x NCG=1 -> 576 blocks

    // conv1 fused over its 3 input segments (src, corr, tgt): 59ch -> 16ch, lrelu
    convb_kernel<16, 27, 16, 4, 16, 12, false>
        <<<g1, blk, sm1>>>(src, corr, tgt, w1, b1, facc, nullptr);
    // conv2 + residual: fsum = f + lrelu(conv(f))
    convb_kernel<16, 0, 0, 4, 16, 12, true>
        <<<g1, blk, sm2>>>(facc, nullptr, nullptr, w2, b2, warped, facc);
    // conv3: 16 -> 3
    convb_kernel<16, 0, 0, 1, 3, 6, false>
        <<<g3, blk, sm2>>>(warped, nullptr, nullptr, w3, b3, out, nullptr);
}